// round 6
// baseline (speedup 1.0000x reference)
#include <cuda_runtime.h>
#include <cstdint>

typedef unsigned long long ULL;
typedef uint32_t U32;

#define C_DIMM 256
#define L_DIMM 2048
#define K_CB   8192
#define M_DIM  16384
#define EMB_N  4194304

// ---------------- smem layout (u32 units) ----------------
#define AP_STR  132                   // u32 per A row (128 pairs + 4 pad)
#define BP_STR  136                   // u32 per B k2-row (128 cw + 8 pad)
#define OFF_AH  0                     // 128*132 = 16896
#define OFF_AL  16896                 // 16896
#define OFF_BP  33792                 // 2 bufs * 16*136 = 4352
#define BP_BUF  2176
#define OFF_SCR 38144                 // 8192 u32 scratch (A staging / kh merge)
#define OFF_XN  46336                 // 128 floats
#define SMEM_U32 46464
#define SMEM_BYTES (SMEM_U32 * 4)     // 185856

__device__ float g_csq[K_CB];
__device__ float g_cmax[1];
__device__ int   g_flag[M_DIM];
__device__ int   g_ncand[M_DIM];
__device__ int   g_cand[M_DIM * 4];
__device__ int   g_code[M_DIM];
__device__ float g_partial[EMB_N / 256];

// ---------------- helpers ----------------
__device__ __forceinline__ U32 smem_u32p(const void* p) {
    U32 a;
    asm("{ .reg .u64 t; cvta.to.shared.u64 t, %1; cvt.u32.u64 %0, t; }" : "=r"(a) : "l"(p));
    return a;
}
__device__ __forceinline__ U32 pack_bf16(float lo, float hi) {
    U32 r; asm("cvt.rn.bf16x2.f32 %0, %1, %2;" : "=r"(r) : "f"(hi), "f"(lo));
    return r;
}
__device__ __forceinline__ ULL makeKey(float s, int gk) {
    unsigned u = __float_as_uint(s);
    u = (u & 0x80000000u) ? ~u : (u | 0x80000000u);
    return ((ULL)u << 32) | (unsigned)(0xFFFFFFFFu - (unsigned)gk);
}
__device__ __forceinline__ float keyVal(ULL k) {
    unsigned v = (unsigned)(k >> 32);
    v = (v & 0x80000000u) ? (v ^ 0x80000000u) : ~v;
    return __uint_as_float(v);
}
__device__ __forceinline__ int keyIdx(ULL k) {
    return (int)(0xFFFFFFFFu - (unsigned)(k & 0xffffffffu));
}
__device__ __forceinline__ ULL maxk(ULL a, ULL b) { return a > b ? a : b; }

__device__ __forceinline__ void ins4(ULL* t, ULL k) {
    if (k > t[3]) {
        t[3] = k;
        if (t[3] > t[2]) { ULL z = t[2]; t[2] = t[3]; t[3] = z;
            if (t[2] > t[1]) { z = t[1]; t[1] = t[2]; t[2] = z;
                if (t[1] > t[0]) { z = t[0]; t[0] = t[1]; t[1] = z; } } }
    }
}

// bf16 legacy tensor mma (sm_80 PTX): D += A(bf16) * B(bf16), fp32 acc
__device__ __forceinline__ void mma16(float* c, const U32* a, U32 b0, U32 b1) {
    asm volatile(
        "mma.sync.aligned.m16n8k16.row.col.f32.bf16.bf16.f32 "
        "{%0,%1,%2,%3}, {%4,%5,%6,%7}, {%8,%9}, {%0,%1,%2,%3};"
        : "+f"(c[0]), "+f"(c[1]), "+f"(c[2]), "+f"(c[3])
        : "r"(a[0]), "r"(a[1]), "r"(a[2]), "r"(a[3]), "r"(b0), "r"(b1));
}
__device__ __forceinline__ void ldsm4(U32* r, U32 addr) {
    asm volatile("ldmatrix.sync.aligned.m8n8.x4.shared.b16 {%0,%1,%2,%3}, [%4];"
        : "=r"(r[0]), "=r"(r[1]), "=r"(r[2]), "=r"(r[3]) : "r"(addr));
}

// ---------------- kernel 1: codebook squared norms ----------------
__global__ void csq_kernel(const float* __restrict__ cb) {
    int k = blockIdx.x * 8 + (threadIdx.x >> 5);
    int lane = threadIdx.x & 31;
    const float* row = cb + (size_t)k * C_DIMM;
    float s = 0.0f;
    #pragma unroll
    for (int c = lane; c < C_DIMM; c += 32) { float v = row[c]; s = fmaf(v, v, s); }
    #pragma unroll
    for (int o = 16; o > 0; o >>= 1) s += __shfl_xor_sync(0xffffffffu, s, o);
    if (lane == 0) g_csq[k] = s;
}

// ---------------- kernel 2: max codebook norm ----------------
__global__ void cmax_kernel() {
    __shared__ float sr[256];
    float m = 0.0f;
    for (int i = threadIdx.x; i < K_CB; i += 256) m = fmaxf(m, g_csq[i]);
    sr[threadIdx.x] = m;
    __syncthreads();
    #pragma unroll
    for (int o = 128; o > 0; o >>= 1) {
        if (threadIdx.x < o) sr[threadIdx.x] = fmaxf(sr[threadIdx.x], sr[threadIdx.x + o]);
        __syncthreads();
    }
    if (threadIdx.x == 0) g_cmax[0] = sqrtf(sr[0]);
}

// ---------------- kernel 3: bf16 split mma GEMM + guaranteed argmax ----------
__global__ __launch_bounds__(256, 1) void argmax_tc(const float* __restrict__ x,
                                                    const float* __restrict__ cb) {
    extern __shared__ U32 smu[];
    float* smf = (float*)smu;
    const U32 base = smem_u32p(smu);

    const int tid = threadIdx.x;
    const int w = tid >> 5, lane = tid & 31;
    const int g = lane >> 2, t = lane & 3;
    const int mwarp = w >> 1, nwarp = w & 1;

    const int rowBase = blockIdx.x * 128;
    const int bidx = rowBase >> 11, l0 = rowBase & 2047;
    const float* xb = x + (size_t)bidx * (C_DIMM * L_DIMM) + l0;

    if (tid < 128) smf[OFF_XN + tid] = 0.0f;
    __syncthreads();

    // ---- stage A: 4 chunks of 64 c: fp32 transpose -> split bf16 planes ----
    for (int cc = 0; cc < 4; ++cc) {
        for (int i = tid; i < 64 * 32; i += 256) {
            int c = i >> 5, m4 = i & 31;
            float4 v = *(const float4*)(xb + (size_t)(cc * 64 + c) * L_DIMM + m4 * 4);
            *(float4*)&smf[OFF_SCR + c * 128 + m4 * 4] = v;
        }
        __syncthreads();
        #pragma unroll
        for (int p = 0; p < 16; ++p) {
            int idx = p * 256 + tid;
            int m = idx & 127, cp = idx >> 7;          // cp 0..31
            float v0 = smf[OFF_SCR + (2 * cp) * 128 + m];
            float v1 = smf[OFF_SCR + (2 * cp + 1) * 128 + m];
            U32 hp = pack_bf16(v0, v1);
            float h0 = __uint_as_float(hp << 16);
            float h1 = __uint_as_float(hp & 0xffff0000u);
            U32 lp = pack_bf16(v0 - h0, v1 - h1);
            smu[OFF_AH + m * AP_STR + cc * 32 + cp] = hp;
            smu[OFF_AL + m * AP_STR + cc * 32 + cp] = lp;
            atomicAdd(&smf[OFF_XN + m], v0 * v0 + v1 * v1);
        }
        __syncthreads();
    }

    // ---- B loader mapping ----
    const int ldcw = tid >> 1;                  // codeword 0..127
    const int ldkh = tid & 1;                   // k half (16 floats)

    // preload gc 0 into buf 0
    {
        const float* src = cb + (size_t)ldcw * C_DIMM + ldkh * 16;
        U32* bsb = smu + OFF_BP;
        #pragma unroll
        for (int j = 0; j < 4; ++j) {
            float4 v = *(const float4*)(src + j * 4);
            int p = ldkh * 8 + j * 2;
            bsb[p * BP_STR + ldcw]       = pack_bf16(v.x, v.y);
            bsb[(p + 1) * BP_STR + ldcw] = pack_bf16(v.z, v.w);
        }
    }
    __syncthreads();

    // per-thread A fragment base offsets (u32 index), add kb2 at use
    const int aRowU = (mwarp * 32 + (lane & 15)) * AP_STR + 4 * (lane >> 4);

    float acc[2][8][4];
    ULL top[4][4];
    #pragma unroll
    for (int s = 0; s < 4; ++s)
        #pragma unroll
        for (int j = 0; j < 4; ++j) top[s][j] = 0ULL;

    for (int gc = 0; gc < 512; ++gc) {          // 64 tiles x 8 k32-chunks
        const int kt = gc >> 3, ch = gc & 7, buf = gc & 1;

        float4 nx[4];
        const bool more = (gc + 1 < 512);
        if (more) {
            const int nkt = (gc + 1) >> 3, nch = (gc + 1) & 7;
            const float* src = cb + (size_t)(nkt * 128 + ldcw) * C_DIMM + nch * 32 + ldkh * 16;
            #pragma unroll
            for (int j = 0; j < 4; ++j) nx[j] = *(const float4*)(src + j * 4);
        }
        if (ch == 0) {
            #pragma unroll
            for (int mt = 0; mt < 2; ++mt)
                #pragma unroll
                for (int nt = 0; nt < 8; ++nt)
                    #pragma unroll
                    for (int j = 0; j < 4; ++j) acc[mt][nt][j] = 0.0f;
        }

        const U32* bsb = smu + OFF_BP + buf * BP_BUF;
        #pragma unroll
        for (int sub = 0; sub < 2; ++sub) {
            const int kb2 = ch * 16 + sub * 8;
            U32 ah[2][4], al[2][4];
            #pragma unroll
            for (int mt = 0; mt < 2; ++mt) {
                U32 aoff = aRowU + mt * 16 * AP_STR + kb2;
                ldsm4(ah[mt], base + (OFF_AH + aoff) * 4);
                ldsm4(al[mt], base + (OFF_AL + aoff) * 4);
            }
            #pragma unroll
            for (int nt = 0; nt < 8; ++nt) {
                const int col = nwarp * 64 + nt * 8 + g;
                U32 b0 = bsb[(sub * 8 + t) * BP_STR + col];
                U32 b1 = bsb[(sub * 8 + 4 + t) * BP_STR + col];
                mma16(acc[0][nt], ah[0], b0, b1);
                mma16(acc[0][nt], al[0], b0, b1);
                mma16(acc[1][nt], ah[1], b0, b1);
                mma16(acc[1][nt], al[1], b0, b1);
            }
        }

        if (more) {
            U32* bd = smu + OFF_BP + (buf ^ 1) * BP_BUF;
            #pragma unroll
            for (int j = 0; j < 4; ++j) {
                int p = ldkh * 8 + j * 2;
                bd[p * BP_STR + ldcw]       = pack_bf16(nx[j].x, nx[j].y);
                bd[(p + 1) * BP_STR + ldcw] = pack_bf16(nx[j].z, nx[j].w);
            }
        }
        __syncthreads();

        if (ch == 7) {  // fold tile scores into per-lane top-4
            const int cb0 = kt * 128 + nwarp * 64 + 2 * t;
            #pragma unroll
            for (int nt = 0; nt < 8; ++nt) {
                int colg = cb0 + nt * 8;
                float2 cq = __ldg((const float2*)&g_csq[colg]);
                #pragma unroll
                for (int mt = 0; mt < 2; ++mt) {
                    float s0 = fmaf(-2.0f, acc[mt][nt][0], cq.x);
                    float s1 = fmaf(-2.0f, acc[mt][nt][1], cq.y);
                    float s2 = fmaf(-2.0f, acc[mt][nt][2], cq.x);
                    float s3 = fmaf(-2.0f, acc[mt][nt][3], cq.y);
                    ins4(top[mt * 2],     makeKey(s0, colg));
                    ins4(top[mt * 2],     makeKey(s1, colg + 1));
                    ins4(top[mt * 2 + 1], makeKey(s2, colg));
                    ins4(top[mt * 2 + 1], makeKey(s3, colg + 1));
                }
            }
        }
    }

    // quad merge (lanes sharing rows differ only in t)
    #pragma unroll
    for (int off = 1; off <= 2; off <<= 1) {
        #pragma unroll
        for (int s = 0; s < 4; ++s) {
            ULL o0 = __shfl_xor_sync(0xffffffffu, top[s][0], off);
            ULL o1 = __shfl_xor_sync(0xffffffffu, top[s][1], off);
            ULL o2 = __shfl_xor_sync(0xffffffffu, top[s][2], off);
            ULL o3 = __shfl_xor_sync(0xffffffffu, top[s][3], off);
            ins4(top[s], o0); ins4(top[s], o1); ins4(top[s], o2); ins4(top[s], o3);
        }
    }

    // cross n-warp merge via scratch (reused as kh)
    ULL* kh = (ULL*)(smu + OFF_SCR);
    if (nwarp == 1 && t == 0) {
        #pragma unroll
        for (int s = 0; s < 4; ++s) {
            int r = mwarp * 32 + (s >> 1) * 16 + (s & 1) * 8 + g;
            #pragma unroll
            for (int j = 0; j < 4; ++j) kh[r * 4 + j] = top[s][j];
        }
    }
    __syncthreads();
    if (nwarp == 0 && t == 0) {
        float cm = g_cmax[0];
        #pragma unroll
        for (int s = 0; s < 4; ++s) {
            int r = mwarp * 32 + (s >> 1) * 16 + (s & 1) * 8 + g;
            #pragma unroll
            for (int j = 0; j < 4; ++j) ins4(top[s], kh[r * 4 + j]);
            float xn = sqrtf(smf[OFF_XN + r]);
            float marg = xn * cm * 0.0078125f + 0.05f;   // 2E (bf16 c-side) + slack
            float v1 = keyVal(top[s][0]), v2 = keyVal(top[s][1]);
            float v3 = keyVal(top[s][2]), v4 = keyVal(top[s][3]);
            int row = rowBase + r;
            int c0 = keyIdx(top[s][0]);
            g_code[row] = c0;
            if (v1 - v4 <= marg) {
                g_flag[row] = 2;                     // full exact rescan
            } else if (v1 - v2 > marg) {
                g_flag[row] = 0;                     // provably exact
            } else {
                int nc = 2;
                g_cand[row * 4 + 0] = c0;
                g_cand[row * 4 + 1] = keyIdx(top[s][1]);
                if (v1 - v3 <= marg) { g_cand[row * 4 + 2] = keyIdx(top[s][2]); nc = 3; }
                g_flag[row] = 1;
                g_ncand[row] = nc;
            }
        }
    }
}

// ---------------- kernel 4: exact-fp32 rescue for flagged rows ----------------
__global__ void rescue_kernel(const float* __restrict__ x, const float* __restrict__ cb) {
    __shared__ float xs[8][C_DIMM];
    int w = threadIdx.x >> 5, lane = threadIdx.x & 31;
    int row = blockIdx.x * 8 + w;
    int fl = g_flag[row];
    if (fl == 0) return;
    int b = row >> 11, l = row & 2047;
    const float* xr = x + (size_t)b * C_DIMM * L_DIMM + l;
    #pragma unroll
    for (int i = 0; i < 8; ++i) xs[w][lane + 32 * i] = xr[(size_t)(lane + 32 * i) * L_DIMM];
    __syncwarp();
    const float4* x4 = (const float4*)xs[w];
    ULL best = 0ULL;
    if (fl == 1) {
        int nc = g_ncand[row];
        if (lane < nc) {
            int k = g_cand[row * 4 + lane];
            const float4* cr = (const float4*)(cb + (size_t)k * C_DIMM);
            float d = 0.0f;
            #pragma unroll 8
            for (int i = 0; i < 64; ++i) {
                float4 a = x4[i], c = cr[i];
                d = fmaf(a.x, c.x, d); d = fmaf(a.y, c.y, d);
                d = fmaf(a.z, c.z, d); d = fmaf(a.w, c.w, d);
            }
            best = makeKey(fmaf(-2.0f, d, g_csq[k]), k);
        }
    } else {
        for (int k = lane; k < K_CB; k += 32) {
            const float4* cr = (const float4*)(cb + (size_t)k * C_DIMM);
            float d = 0.0f;
            #pragma unroll 8
            for (int i = 0; i < 64; ++i) {
                float4 a = x4[i], c = cr[i];
                d = fmaf(a.x, c.x, d); d = fmaf(a.y, c.y, d);
                d = fmaf(a.z, c.z, d); d = fmaf(a.w, c.w, d);
            }
            best = maxk(best, makeKey(fmaf(-2.0f, d, g_csq[k]), k));
        }
    }
    #pragma unroll
    for (int o = 16; o > 0; o >>= 1)
        best = maxk(best, __shfl_xor_sync(0xffffffffu, best, o));
    if (lane == 0) g_code[row] = keyIdx(best);
}

// ---------------- output kernels ----------------
__global__ void code_cast_kernel(float* __restrict__ out_code) {
    int i = blockIdx.x * 256 + threadIdx.x;
    if (i < M_DIM) out_code[i] = (float)g_code[i];
}

__global__ void gather_loss_kernel(const float* __restrict__ x,
                                   const float* __restrict__ cb,
                                   float* __restrict__ emb_out) {
    __shared__ float sred[256];
    int idx = blockIdx.x * 256 + threadIdx.x;
    int bb = idx >> 19;
    int rem = idx & ((1 << 19) - 1);
    int c = rem >> 11;
    int l = rem & (L_DIMM - 1);
    int code = g_code[bb * L_DIMM + l];
    float v = __ldg(&cb[(size_t)code * C_DIMM + c]);
    emb_out[idx] = v;
    float d = x[idx] - v;
    sred[threadIdx.x] = d * d;
    __syncthreads();
    #pragma unroll
    for (int o = 128; o > 0; o >>= 1) {
        if (threadIdx.x < o) sred[threadIdx.x] += sred[threadIdx.x + o];
        __syncthreads();
    }
    if (threadIdx.x == 0) g_partial[blockIdx.x] = sred[0];
}

__global__ void finalize_kernel(float* __restrict__ loss_out) {
    __shared__ float sred[256];
    float s = 0.0f;
    for (int i = threadIdx.x; i < EMB_N / 256; i += 256) s += g_partial[i];
    sred[threadIdx.x] = s;
    __syncthreads();
    #pragma unroll
    for (int o = 128; o > 0; o >>= 1) {
        if (threadIdx.x < o) sred[threadIdx.x] += sred[threadIdx.x + o];
        __syncthreads();
    }
    if (threadIdx.x == 0) loss_out[0] = sred[0] * (1.0f / (float)EMB_N);
}

// ---------------- launch ----------------
extern "C" void kernel_launch(void* const* d_in, const int* in_sizes, int n_in,
                              void* d_out, int out_size) {
    const float* x  = (const float*)d_in[0];   // (8, 256, 2048)
    const float* cb = (const float*)d_in[1];   // (8192, 256)
    float* out = (float*)d_out;

    cudaFuncSetAttribute(argmax_tc, cudaFuncAttributeMaxDynamicSharedMemorySize, SMEM_BYTES);

    csq_kernel<<<K_CB / 8, 256>>>(cb);
    cmax_kernel<<<1, 256>>>();
    argmax_tc<<<M_DIM / 128, 256, SMEM_BYTES>>>(x, cb);
    rescue_kernel<<<M_DIM / 8, 256>>>(x, cb);

    const int full = M_DIM + EMB_N + 1;
    if (out_size >= full) {
        code_cast_kernel<<<(M_DIM + 255) / 256, 256>>>(out);
        gather_loss_kernel<<<EMB_N / 256, 256>>>(x, cb, out + M_DIM);
        finalize_kernel<<<1, 256>>>(out + M_DIM + EMB_N);
    } else if (out_size == EMB_N) {
        gather_loss_kernel<<<EMB_N / 256, 256>>>(x, cb, out);
    } else if (out_size == M_DIM) {
        code_cast_kernel<<<(M_DIM + 255) / 256, 256>>>(out);
    } else {
        gather_loss_kernel<<<EMB_N / 256, 256>>>(x, cb, out);
    }
}